// round 1
// baseline (speedup 1.0000x reference)
#include <cuda_runtime.h>
#include <cstddef>

// Problem shape (fixed by the reference)
#define Bc 2
#define Hc 16
#define Sc 2048
#define Dc 64

// Tiling
#define BM 64     // q rows per block
#define BK 64     // k cols per tile
#define PITCH 65  // smem row pitch (floats) to avoid bank conflicts

// o[b,h,q,d] = sum_k (qk[q,k]*mask[q,k]) * v[k,d] / max(sum_k |qk*mask|, 1)

__global__ __launch_bounds__(256, 2)
void fra_kernel(const float* __restrict__ q,
                const float* __restrict__ k,
                const float* __restrict__ v,
                const float* __restrict__ mask,
                float* __restrict__ o)
{
    extern __shared__ float sm[];
    float* qs   = sm;                    // BM * PITCH
    float* ks   = qs + BM * PITCH;       // BK * PITCH
    float* vs   = ks + BK * PITCH;       // BK * PITCH
    float* ss   = vs + BK * PITCH;       // BM * PITCH (masked scores)
    float* rsum = ss + BM * PITCH;       // BM

    const int tid = threadIdx.x;
    const int tx  = tid & 15;            // k-group / d-group (4 wide)
    const int ty  = tid >> 4;            // q-group (4 wide)
    const int bh  = blockIdx.y;          // b*H + h
    const int q0  = blockIdx.x * BM;

    const float* qg = q    + (size_t)bh * Sc * Dc;
    const float* kg = k    + (size_t)bh * Sc * Dc;
    const float* vg = v    + (size_t)bh * Sc * Dc;
    const float* mg = mask + (size_t)bh * Sc * Sc;
    float*       og = o    + (size_t)bh * Sc * Dc;

    // Load the q tile once (coalesced along d)
    #pragma unroll
    for (int i = 0; i < 16; i++) {
        int idx = tid + i * 256;
        int r = idx >> 6, c = idx & 63;
        qs[r * PITCH + c] = qg[(size_t)(q0 + r) * Dc + c];
    }
    if (tid < BM) rsum[tid] = 0.0f;

    float oacc[16];
    #pragma unroll
    for (int i = 0; i < 16; i++) oacc[i] = 0.0f;
    float racc[4] = {0.0f, 0.0f, 0.0f, 0.0f};

    for (int t = 0; t < Sc; t += BK) {
        __syncthreads();   // previous tile's second GEMM done before overwrite
        #pragma unroll
        for (int i = 0; i < 16; i++) {
            int idx = tid + i * 256;
            int r = idx >> 6, c = idx & 63;
            ks[r * PITCH + c] = kg[(size_t)(t + r) * Dc + c];
            vs[r * PITCH + c] = vg[(size_t)(t + r) * Dc + c];
        }
        __syncthreads();

        // ---- GEMM 1: scores s[4x4] = q_tile @ k_tile^T ----
        float sacc[16];
        #pragma unroll
        for (int i = 0; i < 16; i++) sacc[i] = 0.0f;

        #pragma unroll 8
        for (int d = 0; d < Dc; d++) {
            float a[4], b[4];
            #pragma unroll
            for (int i = 0; i < 4; i++) a[i] = qs[(ty * 4 + i) * PITCH + d];
            #pragma unroll
            for (int j = 0; j < 4; j++) b[j] = ks[(tx * 4 + j) * PITCH + d];
            #pragma unroll
            for (int i = 0; i < 4; i++)
                #pragma unroll
                for (int j = 0; j < 4; j++)
                    sacc[i * 4 + j] = fmaf(a[i], b[j], sacc[i * 4 + j]);
        }

        // ---- mask, abs-accumulate r, stage masked scores ----
        #pragma unroll
        for (int i = 0; i < 4; i++) {
            const int qr = q0 + ty * 4 + i;
            const float* mrow = mg + (size_t)qr * Sc + t;
            #pragma unroll
            for (int j = 0; j < 4; j++) {
                float s = sacc[i * 4 + j] * mrow[tx * 4 + j];
                racc[i] += fabsf(s);
                ss[(ty * 4 + i) * PITCH + tx * 4 + j] = s;
            }
        }
        __syncthreads();

        // ---- GEMM 2: o[4x4] += s_tile @ v_tile ----
        #pragma unroll 8
        for (int kk = 0; kk < BK; kk++) {
            float a[4], b[4];
            #pragma unroll
            for (int i = 0; i < 4; i++) a[i] = ss[(ty * 4 + i) * PITCH + kk];
            #pragma unroll
            for (int j = 0; j < 4; j++) b[j] = vs[kk * PITCH + tx * 4 + j];
            #pragma unroll
            for (int i = 0; i < 4; i++)
                #pragma unroll
                for (int j = 0; j < 4; j++)
                    oacc[i * 4 + j] = fmaf(a[i], b[j], oacc[i * 4 + j]);
        }
    }

    // ---- reduce r across the 16 tx groups, then scaled epilogue ----
    __syncthreads();
    #pragma unroll
    for (int i = 0; i < 4; i++) atomicAdd(&rsum[ty * 4 + i], racc[i]);
    __syncthreads();

    #pragma unroll
    for (int i = 0; i < 4; i++) {
        const int qr = q0 + ty * 4 + i;
        const float rinv = 1.0f / fmaxf(rsum[ty * 4 + i], 1.0f);
        #pragma unroll
        for (int j = 0; j < 4; j++)
            og[(size_t)qr * Dc + tx * 4 + j] = oacc[i * 4 + j] * rinv;
    }
}

extern "C" void kernel_launch(void* const* d_in, const int* in_sizes, int n_in,
                              void* d_out, int out_size)
{
    (void)in_sizes; (void)n_in; (void)out_size;
    const float* q    = (const float*)d_in[0];
    const float* k    = (const float*)d_in[1];
    const float* v    = (const float*)d_in[2];
    const float* mask = (const float*)d_in[3];
    float* o = (float*)d_out;

    const int smem = (4 * BM * PITCH + BM) * (int)sizeof(float);  // 66816 B
    cudaFuncSetAttribute(fra_kernel, cudaFuncAttributeMaxDynamicSharedMemorySize, smem);

    dim3 grid(Sc / BM, Bc * Hc);   // (32, 32)
    dim3 block(256);
    fra_kernel<<<grid, block, smem>>>(q, k, v, mask, o);
}

// round 2
// speedup vs baseline: 2.3507x; 2.3507x over previous
#include <cuda_runtime.h>
#include <cstddef>
#include <cstdint>

// Problem shape (fixed)
#define Bc 2
#define Hc 16
#define Sc 2048
#define Dc 64

// Tiling
#define BM 64     // q rows per block
#define BK 64     // keys per tile
#define PITCH 68  // smem pitch in 32-bit words

// o[b,h,q,d] = sum_k (qk*mask) @ v / max(sum_k |qk*mask|, 1)
// Both GEMMs on tensor pipe via mma.sync m16n8k8 tf32.

__device__ __forceinline__ uint32_t f2tf32(float f) {
    uint32_t u;
    asm("cvt.rna.tf32.f32 %0, %1;" : "=r"(u) : "f"(f));
    return u;
}

__device__ __forceinline__ void mma_tf32(float c[4],
                                         uint32_t a0, uint32_t a1, uint32_t a2, uint32_t a3,
                                         uint32_t b0, uint32_t b1) {
    asm volatile(
        "mma.sync.aligned.m16n8k8.row.col.f32.tf32.tf32.f32 "
        "{%0,%1,%2,%3}, {%4,%5,%6,%7}, {%8,%9}, {%0,%1,%2,%3};"
        : "+f"(c[0]), "+f"(c[1]), "+f"(c[2]), "+f"(c[3])
        : "r"(a0), "r"(a1), "r"(a2), "r"(a3), "r"(b0), "r"(b1));
}

__global__ __launch_bounds__(256, 2)
void fra_mma_kernel(const float* __restrict__ q,
                    const float* __restrict__ k,
                    const float* __restrict__ v,
                    const float* __restrict__ mask,
                    float* __restrict__ o)
{
    extern __shared__ uint32_t smw[];
    uint32_t* qs = smw;                   // BM x PITCH (tf32 bits)
    uint32_t* ks = qs + BM * PITCH;       // BK x PITCH
    uint32_t* vs = ks + BK * PITCH;       // BK x PITCH
    uint32_t* ss = vs + BK * PITCH;       // BM x PITCH (masked scores, tf32)
    float* rsum  = (float*)(ss + BM * PITCH);  // BM

    const int tid  = threadIdx.x;
    const int wid  = tid >> 5;
    const int lane = tid & 31;
    const int gid  = lane >> 2;   // 0..7
    const int tig  = lane & 3;    // 0..3
    const int wm   = wid & 3;     // warp m block (16 rows)
    const int wn   = wid >> 2;    // warp n block (32 cols)
    const int bh   = blockIdx.y;
    const int q0   = blockIdx.x * BM;

    const float* qg = q    + (size_t)bh * Sc * Dc;
    const float* kg = k    + (size_t)bh * Sc * Dc;
    const float* vg = v    + (size_t)bh * Sc * Dc;
    const float* mg = mask + (size_t)bh * Sc * Sc;
    float*       og = o    + (size_t)bh * Sc * Dc;

    // ---- load Q tile once, convert to tf32 ----
    #pragma unroll
    for (int i = 0; i < 4; i++) {
        int fi = tid + i * 256;            // float4 index, 1024 total
        int r  = fi >> 4;
        int c4 = (fi & 15) * 4;
        float4 x = *(const float4*)(qg + (size_t)(q0 + r) * Dc + c4);
        qs[r * PITCH + c4 + 0] = f2tf32(x.x);
        qs[r * PITCH + c4 + 1] = f2tf32(x.y);
        qs[r * PITCH + c4 + 2] = f2tf32(x.z);
        qs[r * PITCH + c4 + 3] = f2tf32(x.w);
    }
    if (tid < BM) rsum[tid] = 0.0f;

    float oacc[4][4];
    #pragma unroll
    for (int j = 0; j < 4; j++)
        #pragma unroll
        for (int r = 0; r < 4; r++) oacc[j][r] = 0.0f;
    float racc0 = 0.0f, racc1 = 0.0f;

    const int arow0 = (wm * 16 + gid) * PITCH;      // fragment row base
    const int arow1 = (wm * 16 + gid + 8) * PITCH;

    for (int t = 0; t < Sc; t += BK) {
        __syncthreads();  // previous GEMM2 done before overwriting ks/vs

        // ---- load K/V tiles, convert to tf32 ----
        #pragma unroll
        for (int i = 0; i < 4; i++) {
            int fi = tid + i * 256;
            int r  = fi >> 4;
            int c4 = (fi & 15) * 4;
            float4 xk = *(const float4*)(kg + (size_t)(t + r) * Dc + c4);
            float4 xv = *(const float4*)(vg + (size_t)(t + r) * Dc + c4);
            ks[r * PITCH + c4 + 0] = f2tf32(xk.x);
            ks[r * PITCH + c4 + 1] = f2tf32(xk.y);
            ks[r * PITCH + c4 + 2] = f2tf32(xk.z);
            ks[r * PITCH + c4 + 3] = f2tf32(xk.w);
            vs[r * PITCH + c4 + 0] = f2tf32(xv.x);
            vs[r * PITCH + c4 + 1] = f2tf32(xv.y);
            vs[r * PITCH + c4 + 2] = f2tf32(xv.z);
            vs[r * PITCH + c4 + 3] = f2tf32(xv.w);
        }
        __syncthreads();

        // ---- GEMM1: S = Q @ K^T  (warp: 16x32 of the 64x64 tile) ----
        float sacc[4][4];
        #pragma unroll
        for (int j = 0; j < 4; j++)
            #pragma unroll
            for (int r = 0; r < 4; r++) sacc[j][r] = 0.0f;

        #pragma unroll
        for (int kk = 0; kk < 8; kk++) {
            const int kc = kk * 8 + tig;
            uint32_t a0 = qs[arow0 + kc];
            uint32_t a1 = qs[arow1 + kc];
            uint32_t a2 = qs[arow0 + kc + 4];
            uint32_t a3 = qs[arow1 + kc + 4];
            #pragma unroll
            for (int j = 0; j < 4; j++) {
                const int nrow = (wn * 32 + j * 8 + gid) * PITCH;
                uint32_t b0 = ks[nrow + kc];
                uint32_t b1 = ks[nrow + kc + 4];
                mma_tf32(sacc[j], a0, a1, a2, a3, b0, b1);
            }
        }

        // ---- mask in registers, abs-accumulate, stage tf32 scores ----
        const size_t mrow0 = (size_t)(q0 + wm * 16 + gid) * Sc + t;
        #pragma unroll
        for (int j = 0; j < 4; j++) {
            const int col = wn * 32 + j * 8 + 2 * tig;
            float2 m0 = *(const float2*)(mg + mrow0 + col);
            float2 m1 = *(const float2*)(mg + mrow0 + (size_t)8 * Sc + col);
            float s0 = sacc[j][0] * m0.x;
            float s1 = sacc[j][1] * m0.y;
            float s2 = sacc[j][2] * m1.x;
            float s3 = sacc[j][3] * m1.y;
            racc0 += fabsf(s0) + fabsf(s1);
            racc1 += fabsf(s2) + fabsf(s3);
            uint2 p0; p0.x = f2tf32(s0); p0.y = f2tf32(s1);
            uint2 p1; p1.x = f2tf32(s2); p1.y = f2tf32(s3);
            *(uint2*)(ss + arow0 + col) = p0;
            *(uint2*)(ss + arow1 + col) = p1;
        }
        __syncthreads();

        // ---- GEMM2: O += S~ @ V  (warp: 16x32 of 64x64 output) ----
        #pragma unroll
        for (int kk = 0; kk < 8; kk++) {
            const int kc = kk * 8 + tig;
            uint32_t a0 = ss[arow0 + kc];
            uint32_t a1 = ss[arow1 + kc];
            uint32_t a2 = ss[arow0 + kc + 4];
            uint32_t a3 = ss[arow1 + kc + 4];
            const int vrow0 = (kk * 8 + tig) * PITCH;
            const int vrow1 = (kk * 8 + tig + 4) * PITCH;
            #pragma unroll
            for (int j = 0; j < 4; j++) {
                const int nc = wn * 32 + j * 8 + gid;
                uint32_t b0 = vs[vrow0 + nc];
                uint32_t b1 = vs[vrow1 + nc];
                mma_tf32(oacc[j], a0, a1, a2, a3, b0, b1);
            }
        }
    }

    // ---- reduce row abs-sums: within quad, then across the 2 n-warps ----
    racc0 += __shfl_xor_sync(0xffffffffu, racc0, 1);
    racc0 += __shfl_xor_sync(0xffffffffu, racc0, 2);
    racc1 += __shfl_xor_sync(0xffffffffu, racc1, 1);
    racc1 += __shfl_xor_sync(0xffffffffu, racc1, 2);
    if (tig == 0) {
        atomicAdd(&rsum[wm * 16 + gid], racc0);
        atomicAdd(&rsum[wm * 16 + gid + 8], racc1);
    }
    __syncthreads();

    const float rinv0 = 1.0f / fmaxf(rsum[wm * 16 + gid], 1.0f);
    const float rinv1 = 1.0f / fmaxf(rsum[wm * 16 + gid + 8], 1.0f);
    const size_t orow0 = (size_t)(q0 + wm * 16 + gid) * Dc;
    #pragma unroll
    for (int j = 0; j < 4; j++) {
        const int col = wn * 32 + j * 8 + 2 * tig;
        float2 y0; y0.x = oacc[j][0] * rinv0; y0.y = oacc[j][1] * rinv0;
        float2 y1; y1.x = oacc[j][2] * rinv1; y1.y = oacc[j][3] * rinv1;
        *(float2*)(og + orow0 + col) = y0;
        *(float2*)(og + orow0 + (size_t)8 * Dc + col) = y1;
    }
}

extern "C" void kernel_launch(void* const* d_in, const int* in_sizes, int n_in,
                              void* d_out, int out_size)
{
    (void)in_sizes; (void)n_in; (void)out_size;
    const float* q    = (const float*)d_in[0];
    const float* k    = (const float*)d_in[1];
    const float* v    = (const float*)d_in[2];
    const float* mask = (const float*)d_in[3];
    float* o = (float*)d_out;

    const int smem = (4 * BM * PITCH) * 4 + BM * 4;  // 69888 B
    cudaFuncSetAttribute(fra_mma_kernel, cudaFuncAttributeMaxDynamicSharedMemorySize, smem);

    dim3 grid(Sc / BM, Bc * Hc);   // (32, 32)
    fra_mma_kernel<<<grid, 256, smem>>>(q, k, v, mask, o);
}

// round 4
// speedup vs baseline: 2.9650x; 1.2613x over previous
#include <cuda_runtime.h>
#include <cstddef>
#include <cstdint>

// Problem shape (fixed)
#define Bc 2
#define Hc 16
#define Sc 2048
#define Dc 64

// Tiling
#define BM 64    // q rows per block
#define BK 64    // keys per tile
#define KP 68    // qs/ks pitch (mod 32 == 4  -> conflict-free A/B frag loads)
#define VP 72    // vs pitch    (mod 32 == 8  -> conflict-free GEMM2 B loads)
#define RP 66    // reduction buffer pitch (even for float2 alignment)

__device__ __forceinline__ uint32_t f2tf32(float f) {
    uint32_t u;
    asm("cvt.rna.tf32.f32 %0, %1;" : "=r"(u) : "f"(f));
    return u;
}

__device__ __forceinline__ void mma_tf32(float c[4],
                                         uint32_t a0, uint32_t a1, uint32_t a2, uint32_t a3,
                                         uint32_t b0, uint32_t b1) {
    asm volatile(
        "mma.sync.aligned.m16n8k8.row.col.f32.tf32.tf32.f32 "
        "{%0,%1,%2,%3}, {%4,%5,%6,%7}, {%8,%9}, {%0,%1,%2,%3};"
        : "+f"(c[0]), "+f"(c[1]), "+f"(c[2]), "+f"(c[3])
        : "r"(a0), "r"(a1), "r"(a2), "r"(a3), "r"(b0), "r"(b1));
}

__global__ __launch_bounds__(256, 2)
void fra_mma3_kernel(const float* __restrict__ q,
                     const float* __restrict__ k,
                     const float* __restrict__ v,
                     const float* __restrict__ mask,
                     float* __restrict__ o)
{
    extern __shared__ uint32_t smw[];
    uint32_t* qs = smw;                   // BM x KP
    uint32_t* ks = qs + BM * KP;          // BK x KP
    uint32_t* vs = ks + BK * KP;          // BK x VP
    float* rsum  = (float*)(vs + BK * VP);  // BM
    float* red   = (float*)ks;            // reused at epilogue: BM x RP

    const int tid  = threadIdx.x;
    const int wid  = tid >> 5;
    const int lane = tid & 31;
    const int gid  = lane >> 2;   // 0..7
    const int tig  = lane & 3;    // 0..3
    const int wm   = wid & 3;     // 16-row m strip
    const int wk   = wid >> 2;    // 32-col k strip (GEMM2 k-split)
    const int bh   = blockIdx.y;
    const int q0   = blockIdx.x * BM;

    const float* qg = q    + (size_t)bh * Sc * Dc;
    const float* kg = k    + (size_t)bh * Sc * Dc;
    const float* vg = v    + (size_t)bh * Sc * Dc;
    const float* mg = mask + (size_t)bh * Sc * Sc;
    float*       og = o    + (size_t)bh * Sc * Dc;

    // ---- load Q tile once (tf32, vectorized) ----
    #pragma unroll
    for (int i = 0; i < 4; i++) {
        int fi = tid + i * 256;
        int r  = fi >> 4;
        int c4 = (fi & 15) * 4;
        float4 x = *(const float4*)(qg + (size_t)(q0 + r) * Dc + c4);
        uint4 y;
        y.x = f2tf32(x.x); y.y = f2tf32(x.y); y.z = f2tf32(x.z); y.w = f2tf32(x.w);
        *(uint4*)(qs + r * KP + c4) = y;
    }
    if (tid < BM) rsum[tid] = 0.0f;

    float oacc[8][4];
    #pragma unroll
    for (int j = 0; j < 8; j++)
        #pragma unroll
        for (int r = 0; r < 4; r++) oacc[j][r] = 0.0f;
    float racc0 = 0.0f, racc1 = 0.0f;

    const int arow0 = (wm * 16 + gid) * KP;
    const int arow1 = (wm * 16 + gid + 8) * KP;

    for (int t = 0; t < Sc; t += BK) {
        __syncthreads();  // previous tile fully consumed

        // ---- stage K/V tiles as tf32 (STS.128) ----
        #pragma unroll
        for (int i = 0; i < 4; i++) {
            int fi = tid + i * 256;
            int r  = fi >> 4;
            int c4 = (fi & 15) * 4;
            float4 xk = *(const float4*)(kg + (size_t)(t + r) * Dc + c4);
            float4 xv = *(const float4*)(vg + (size_t)(t + r) * Dc + c4);
            uint4 yk, yv;
            yk.x = f2tf32(xk.x); yk.y = f2tf32(xk.y); yk.z = f2tf32(xk.z); yk.w = f2tf32(xk.w);
            yv.x = f2tf32(xv.x); yv.y = f2tf32(xv.y); yv.z = f2tf32(xv.z); yv.w = f2tf32(xv.w);
            *(uint4*)(ks + r * KP + c4) = yk;
            *(uint4*)(vs + r * VP + c4) = yv;
        }
        __syncthreads();

        // ---- GEMM1: S(16x32) = Q @ K^T over this warp's (wm, wk) strip ----
        float sacc[4][4];
        #pragma unroll
        for (int j = 0; j < 4; j++)
            #pragma unroll
            for (int r = 0; r < 4; r++) sacc[j][r] = 0.0f;

        #pragma unroll
        for (int kk = 0; kk < 8; kk++) {
            const int kc = kk * 8 + tig;
            uint32_t a0 = qs[arow0 + kc];
            uint32_t a1 = qs[arow1 + kc];
            uint32_t a2 = qs[arow0 + kc + 4];
            uint32_t a3 = qs[arow1 + kc + 4];
            #pragma unroll
            for (int j = 0; j < 4; j++) {
                const int nr = (wk * 32 + j * 8 + gid) * KP;
                uint32_t b0 = ks[nr + kc];
                uint32_t b1 = ks[nr + kc + 4];
                mma_tf32(sacc[j], a0, a1, a2, a3, b0, b1);
            }
        }

        // ---- mask + abs-sum + in-register permute to GEMM2 A fragments ----
        const float* mbase = mg + (size_t)(q0 + wm * 16 + gid) * Sc + t + wk * 32;
        uint32_t afrag[4][4];
        const int s0 = tig >> 1;
        const int s2 = s0 + 2;
        const bool od = (tig & 1) != 0;
        #pragma unroll
        for (int j = 0; j < 4; j++) {
            const int col = j * 8 + 2 * tig;
            float2 m0 = *(const float2*)(mbase + col);
            float2 m1 = *(const float2*)(mbase + (size_t)8 * Sc + col);
            float c0 = sacc[j][0] * m0.x;   // (gid,   2tig)
            float c1 = sacc[j][1] * m0.y;   // (gid,   2tig+1)
            float c2 = sacc[j][2] * m1.x;   // (gid+8, 2tig)
            float c3 = sacc[j][3] * m1.y;   // (gid+8, 2tig+1)
            racc0 += fabsf(c0) + fabsf(c1);
            racc1 += fabsf(c2) + fabsf(c3);
            // permute within quad: owner of col c is lane (c>>1), slot (c&1)
            float x00 = __shfl_sync(0xffffffffu, c0, s0, 4);
            float x01 = __shfl_sync(0xffffffffu, c1, s0, 4);
            float x20 = __shfl_sync(0xffffffffu, c0, s2, 4);
            float x21 = __shfl_sync(0xffffffffu, c1, s2, 4);
            float y00 = __shfl_sync(0xffffffffu, c2, s0, 4);
            float y01 = __shfl_sync(0xffffffffu, c3, s0, 4);
            float y20 = __shfl_sync(0xffffffffu, c2, s2, 4);
            float y21 = __shfl_sync(0xffffffffu, c3, s2, 4);
            afrag[j][0] = f2tf32(od ? x01 : x00);  // (gid,   tig)
            afrag[j][1] = f2tf32(od ? y01 : y00);  // (gid+8, tig)
            afrag[j][2] = f2tf32(od ? x21 : x20);  // (gid,   tig+4)
            afrag[j][3] = f2tf32(od ? y21 : y20);  // (gid+8, tig+4)
        }

        // ---- GEMM2: O_partial(16x64) += S~ @ V over this warp's k strip ----
        #pragma unroll
        for (int kk2 = 0; kk2 < 4; kk2++) {
            const int vr = (wk * 32 + kk2 * 8 + tig) * VP;
            #pragma unroll
            for (int j2 = 0; j2 < 8; j2++) {
                uint32_t b0 = vs[vr + j2 * 8 + gid];
                uint32_t b1 = vs[vr + 4 * VP + j2 * 8 + gid];
                mma_tf32(oacc[j2], afrag[kk2][0], afrag[kk2][1],
                         afrag[kk2][2], afrag[kk2][3], b0, b1);
            }
        }
    }

    // ---- row abs-sum reduction ----
    racc0 += __shfl_xor_sync(0xffffffffu, racc0, 1);
    racc0 += __shfl_xor_sync(0xffffffffu, racc0, 2);
    racc1 += __shfl_xor_sync(0xffffffffu, racc1, 1);
    racc1 += __shfl_xor_sync(0xffffffffu, racc1, 2);
    if (tig == 0) {
        atomicAdd(&rsum[wm * 16 + gid], racc0);
        atomicAdd(&rsum[wm * 16 + gid + 8], racc1);
    }
    __syncthreads();

    // ---- cross-wk partial-O reduction via smem, then scaled writeout ----
    if (wk == 1) {
        #pragma unroll
        for (int j2 = 0; j2 < 8; j2++) {
            const int col = j2 * 8 + 2 * tig;
            float2 p0; p0.x = oacc[j2][0]; p0.y = oacc[j2][1];
            float2 p1; p1.x = oacc[j2][2]; p1.y = oacc[j2][3];
            *(float2*)(red + (wm * 16 + gid) * RP + col) = p0;
            *(float2*)(red + (wm * 16 + gid + 8) * RP + col) = p1;
        }
    }
    __syncthreads();
    if (wk == 0) {
        const float rinv0 = 1.0f / fmaxf(rsum[wm * 16 + gid], 1.0f);
        const float rinv1 = 1.0f / fmaxf(rsum[wm * 16 + gid + 8], 1.0f);
        const size_t orow0 = (size_t)(q0 + wm * 16 + gid) * Dc;
        #pragma unroll
        for (int j2 = 0; j2 < 8; j2++) {
            const int col = j2 * 8 + 2 * tig;
            float2 p0 = *(const float2*)(red + (wm * 16 + gid) * RP + col);
            float2 p1 = *(const float2*)(red + (wm * 16 + gid + 8) * RP + col);
            float2 y0, y1;
            y0.x = (oacc[j2][0] + p0.x) * rinv0;
            y0.y = (oacc[j2][1] + p0.y) * rinv0;
            y1.x = (oacc[j2][2] + p1.x) * rinv1;
            y1.y = (oacc[j2][3] + p1.y) * rinv1;
            *(float2*)(og + orow0 + col) = y0;
            *(float2*)(og + orow0 + (size_t)8 * Dc + col) = y1;
        }
    }
}

extern "C" void kernel_launch(void* const* d_in, const int* in_sizes, int n_in,
                              void* d_out, int out_size)
{
    (void)in_sizes; (void)n_in; (void)out_size;
    const float* q    = (const float*)d_in[0];
    const float* k    = (const float*)d_in[1];
    const float* v    = (const float*)d_in[2];
    const float* mask = (const float*)d_in[3];
    float* o = (float*)d_out;

    const int smem = (BM * KP + BK * KP + BK * VP + BM) * 4;  // 53504 B
    cudaFuncSetAttribute(fra_mma3_kernel, cudaFuncAttributeMaxDynamicSharedMemorySize, smem);

    dim3 grid(Sc / BM, Bc * Hc);   // (32, 32)
    fra_mma3_kernel<<<grid, 256, smem>>>(q, k, v, mask, o);
}

// round 6
// speedup vs baseline: 3.0379x; 1.0246x over previous
#include <cuda_runtime.h>
#include <cstdint>
#include <cstddef>

// Problem shape (fixed)
#define Bc 2
#define Hc 16
#define Sc 2048
#define Dc 64

// Tiling
#define BM 128            // q rows per CTA
#define BK 64             // keys per tile
#define NT (Sc / BK)      // 32 tiles
#define KP 68             // q/k smem pitch (words); 68%32==4 -> conflict-free ldmatrix
#define VP 72             // v smem pitch   (words); 72%32==8 -> conflict-free B loads

// SMEM byte offsets
#define SM_Q   0
#define SM_K0  (BM * KP * 4)              // 34816
#define SM_K1  (SM_K0 + BK * KP * 4)      // 52224
#define SM_V0  (SM_K1 + BK * KP * 4)      // 69632
#define SM_V1  (SM_V0 + BK * VP * 4)      // 88064
#define SM_TOT (SM_V1 + BK * VP * 4)      // 106496

static __device__ __forceinline__ uint32_t smem_u32(const void* p) {
    uint32_t a;
    asm("{ .reg .u64 t; cvta.to.shared.u64 t, %1; cvt.u32.u64 %0, t; }"
        : "=r"(a) : "l"(p));
    return a;
}
static __device__ __forceinline__ uint32_t f2tf32(float f) {
    uint32_t u;
    asm("cvt.rna.tf32.f32 %0, %1;" : "=r"(u) : "f"(f));
    return u;
}
static __device__ __forceinline__ void mma_tf32(float c[4],
                                                uint32_t a0, uint32_t a1, uint32_t a2, uint32_t a3,
                                                uint32_t b0, uint32_t b1) {
    asm volatile(
        "mma.sync.aligned.m16n8k8.row.col.f32.tf32.tf32.f32 "
        "{%0,%1,%2,%3}, {%4,%5,%6,%7}, {%8,%9}, {%0,%1,%2,%3};"
        : "+f"(c[0]), "+f"(c[1]), "+f"(c[2]), "+f"(c[3])
        : "r"(a0), "r"(a1), "r"(a2), "r"(a3), "r"(b0), "r"(b1));
}
static __device__ __forceinline__ void ldsm4(uint32_t& r0, uint32_t& r1,
                                             uint32_t& r2, uint32_t& r3, uint32_t a) {
    asm volatile("ldmatrix.sync.aligned.m8n8.x4.shared.b16 {%0,%1,%2,%3}, [%4];"
                 : "=r"(r0), "=r"(r1), "=r"(r2), "=r"(r3) : "r"(a));
}
static __device__ __forceinline__ void cp16(uint32_t dst, const void* src) {
    asm volatile("cp.async.cg.shared.global [%0], [%1], 16;"
                 :: "r"(dst), "l"(src) : "memory");
}

// Issue one K/V tile into a stage (raw f32, 16B chunks, pitched dst)
static __device__ __forceinline__ void issue_tile(uint32_t sb, int stage, int t, int tid,
                                                  const float* kg, const float* vg) {
    const uint32_t kbase = sb + (stage ? SM_K1 : SM_K0);
    const uint32_t vbase = sb + (stage ? SM_V1 : SM_V0);
    #pragma unroll
    for (int i = 0; i < 4; i++) {
        int fi = tid + i * 256;
        int r = fi >> 4, c4 = (fi & 15) * 4;
        cp16(kbase + (uint32_t)(r * KP + c4) * 4, kg + (size_t)(t + r) * Dc + c4);
        cp16(vbase + (uint32_t)(r * VP + c4) * 4, vg + (size_t)(t + r) * Dc + c4);
    }
    asm volatile("cp.async.commit_group;" ::: "memory");
}

__global__ __launch_bounds__(256, 2)
void fra_mma4_kernel(const float* __restrict__ q,
                     const float* __restrict__ k,
                     const float* __restrict__ v,
                     const float* __restrict__ mask,
                     float* __restrict__ o)
{
    extern __shared__ char smem[];
    const uint32_t sb = smem_u32(smem);
    const int tid  = threadIdx.x;
    const int lane = tid & 31;
    const int wid  = tid >> 5;
    const int gid  = lane >> 2;
    const int tig  = lane & 3;
    const int mbase = wid * 16;            // warp's 16-row strip
    const int bh = blockIdx.y;
    const int q0 = blockIdx.x * BM;

    const float* qg = q    + (size_t)bh * Sc * Dc;
    const float* kg = k    + (size_t)bh * Sc * Dc;
    const float* vg = v    + (size_t)bh * Sc * Dc;
    const float* mg = mask + (size_t)bh * Sc * Sc;
    float*       og = o    + (size_t)bh * Sc * Dc;

    // ---- stage Q once (tf32, pitched) ----
    #pragma unroll
    for (int i = 0; i < 8; i++) {
        int fi = tid + i * 256;
        int r = fi >> 4, c4 = (fi & 15) * 4;
        float4 x = *(const float4*)(qg + (size_t)(q0 + r) * Dc + c4);
        uint4 y;
        y.x = f2tf32(x.x); y.y = f2tf32(x.y); y.z = f2tf32(x.z); y.w = f2tf32(x.w);
        *(uint4*)(smem + SM_Q + (size_t)(r * KP + c4) * 4) = y;
    }
    issue_tile(sb, 0, 0, tid, kg, vg);

    // per-thread ldmatrix address components (row-in-16, col offset)
    const int lrow = (lane & 7) + 8 * ((lane >> 3) & 1);
    const int lcol = 4 * (lane >> 4);
    const uint32_t aAddr0 = sb + SM_Q + (uint32_t)((mbase + lrow) * KP + lcol) * 4;

    float oacc[8][4];
    #pragma unroll
    for (int d = 0; d < 8; d++)
        #pragma unroll
        for (int r = 0; r < 4; r++) oacc[d][r] = 0.0f;
    float racc0 = 0.0f, racc1 = 0.0f;

    const float* mr0 = mg + (size_t)(q0 + mbase + gid) * Sc;
    const float* mr1 = mr0 + (size_t)8 * Sc;

    const int s0l = tig >> 1;          // permute source lanes (quad)
    const int s2l = s0l + 2;
    const bool od = (tig & 1) != 0;

    for (int tt = 0; tt < NT; tt++) {
        const int t = tt * BK;
        if (tt + 1 < NT) {
            issue_tile(sb, (tt + 1) & 1, t + BK, tid, kg, vg);
            asm volatile("cp.async.wait_group 1;" ::: "memory");
        } else {
            asm volatile("cp.async.wait_group 0;" ::: "memory");
        }
        __syncthreads();

        const uint32_t kb  = sb + ((tt & 1) ? SM_K1 : SM_K0);
        const float*   vsm = (const float*)(smem + ((tt & 1) ? SM_V1 : SM_V0));

        // ---- GEMM1: S(16x64) = Q @ K^T (raw K frags cvt'd in regs) ----
        float sacc[8][4];
        #pragma unroll
        for (int j = 0; j < 8; j++)
            #pragma unroll
            for (int r = 0; r < 4; r++) sacc[j][r] = 0.0f;

        #pragma unroll
        for (int s = 0; s < 8; s++) {
            uint32_t a0, a1, a2, a3;
            ldsm4(a0, a1, a2, a3, aAddr0 + (uint32_t)s * 32);
            #pragma unroll
            for (int p = 0; p < 4; p++) {
                uint32_t t0, t1, t2, t3;
                ldsm4(t0, t1, t2, t3,
                      kb + (uint32_t)((16 * p + lrow) * KP + 8 * s + lcol) * 4);
                uint32_t b00 = f2tf32(__uint_as_float(t0));  // b0, j=2p
                uint32_t b01 = f2tf32(__uint_as_float(t1));  // b0, j=2p+1
                uint32_t b10 = f2tf32(__uint_as_float(t2));  // b1, j=2p
                uint32_t b11 = f2tf32(__uint_as_float(t3));  // b1, j=2p+1
                mma_tf32(sacc[2 * p],     a0, a1, a2, a3, b00, b10);
                mma_tf32(sacc[2 * p + 1], a0, a1, a2, a3, b01, b11);
            }
        }

        // ---- per key-group: mask, abs-sum, permute -> A frag, GEMM2 ----
        float2 m0 = *(const float2*)(mr0 + t + 2 * tig);
        float2 m1 = *(const float2*)(mr1 + t + 2 * tig);
        #pragma unroll
        for (int j = 0; j < 8; j++) {
            float2 n0 = m0, n1 = m1;
            if (j < 7) {
                n0 = *(const float2*)(mr0 + t + 8 * (j + 1) + 2 * tig);
                n1 = *(const float2*)(mr1 + t + 8 * (j + 1) + 2 * tig);
            }
            float c0 = sacc[j][0] * m0.x;   // (row gid,   key 8j+2tig)
            float c1 = sacc[j][1] * m0.y;   // (row gid,   key 8j+2tig+1)
            float c2 = sacc[j][2] * m1.x;   // (row gid+8, ...)
            float c3 = sacc[j][3] * m1.y;
            racc0 += fabsf(c0) + fabsf(c1);
            racc1 += fabsf(c2) + fabsf(c3);

            // quad permute: accumulator cols (2tig,2tig+1) -> A-frag cols (tig, tig+4)
            float x00 = __shfl_sync(0xffffffffu, c0, s0l, 4);
            float x01 = __shfl_sync(0xffffffffu, c1, s0l, 4);
            float x20 = __shfl_sync(0xffffffffu, c0, s2l, 4);
            float x21 = __shfl_sync(0xffffffffu, c1, s2l, 4);
            float y00 = __shfl_sync(0xffffffffu, c2, s0l, 4);
            float y01 = __shfl_sync(0xffffffffu, c3, s0l, 4);
            float y20 = __shfl_sync(0xffffffffu, c2, s2l, 4);
            float y21 = __shfl_sync(0xffffffffu, c3, s2l, 4);
            uint32_t a0 = f2tf32(od ? x01 : x00);  // (gid,   k=tig)
            uint32_t a1 = f2tf32(od ? y01 : y00);  // (gid+8, k=tig)
            uint32_t a2 = f2tf32(od ? x21 : x20);  // (gid,   k=tig+4)
            uint32_t a3 = f2tf32(od ? y21 : y20);  // (gid+8, k=tig+4)

            const int vr0 = (8 * j + tig) * VP + gid;
            const int vr1 = (8 * j + 4 + tig) * VP + gid;
            #pragma unroll
            for (int db = 0; db < 8; db++) {
                uint32_t b0 = f2tf32(vsm[vr0 + 8 * db]);
                uint32_t b1 = f2tf32(vsm[vr1 + 8 * db]);
                mma_tf32(oacc[db], a0, a1, a2, a3, b0, b1);
            }
            m0 = n0; m1 = n1;
        }
        __syncthreads();   // all reads of this stage done before its re-fill
    }

    // ---- warp-local row abs-sums (warp owns full rows) ----
    racc0 += __shfl_xor_sync(0xffffffffu, racc0, 1);
    racc0 += __shfl_xor_sync(0xffffffffu, racc0, 2);
    racc1 += __shfl_xor_sync(0xffffffffu, racc1, 1);
    racc1 += __shfl_xor_sync(0xffffffffu, racc1, 2);
    const float rinv0 = 1.0f / fmaxf(racc0, 1.0f);
    const float rinv1 = 1.0f / fmaxf(racc1, 1.0f);

    float* or0 = og + (size_t)(q0 + mbase + gid) * Dc;
    float* or1 = or0 + (size_t)8 * Dc;
    #pragma unroll
    for (int db = 0; db < 8; db++) {
        const int col = 8 * db + 2 * tig;
        float2 y0, y1;
        y0.x = oacc[db][0] * rinv0; y0.y = oacc[db][1] * rinv0;
        y1.x = oacc[db][2] * rinv1; y1.y = oacc[db][3] * rinv1;
        *(float2*)(or0 + col) = y0;
        *(float2*)(or1 + col) = y1;
    }
}

extern "C" void kernel_launch(void* const* d_in, const int* in_sizes, int n_in,
                              void* d_out, int out_size)
{
    (void)in_sizes; (void)n_in; (void)out_size;
    const float* q    = (const float*)d_in[0];
    const float* k    = (const float*)d_in[1];
    const float* v    = (const float*)d_in[2];
    const float* mask = (const float*)d_in[3];
    float* o = (float*)d_out;

    cudaFuncSetAttribute(fra_mma4_kernel,
                         cudaFuncAttributeMaxDynamicSharedMemorySize, SM_TOT);

    dim3 grid(Sc / BM, Bc * Hc);   // (16, 32)
    fra_mma4_kernel<<<grid, 256, SM_TOT>>>(q, k, v, mask, o);
}